// round 5
// baseline (speedup 1.0000x reference)
#include <cuda_runtime.h>
#include <cuda_fp16.h>

// ---------------- scratch (no cudaMalloc allowed) ----------------
__device__ float g_h1[256 * 1024 * 8];   // LSTM1 outputs, [B][S][8], 8MB

// ---------------- fast activations (MUFU.TANH based) ----------------
__device__ __forceinline__ float tanhapx(float x) {
    float r; asm("tanh.approx.f32 %0, %1;" : "=f"(r) : "f"(x)); return r;
}
__device__ __forceinline__ float sigf(float x) {
    return fmaf(0.5f, tanhapx(0.5f * x), 0.5f);
}
__device__ __forceinline__ float tanh_(float x) { return tanhapx(x); }

__device__ __forceinline__ float dot4(float4 w, float4 v, float a) {
    a = fmaf(w.x, v.x, a); a = fmaf(w.y, v.y, a);
    a = fmaf(w.z, v.z, a); a = fmaf(w.w, v.w, a);
    return a;
}

// =================================================================
// Kernel 1: LSTM1. One thread per (b,s) sequence: 16 steps, input=1, H=8.
// =================================================================
__global__ __launch_bounds__(256) void lstm1_kernel(
    const float* __restrict__ x,
    const float* __restrict__ W_ih1, const float* __restrict__ W_hh1,
    const float* __restrict__ b_ih1, const float* __restrict__ b_hh1)
{
    __shared__ float sw_ih[32];
    __shared__ float sw_hh[32][8];
    __shared__ float sbias[32];
    int tid = threadIdx.x;
    if (tid < 32) { sw_ih[tid] = W_ih1[tid]; sbias[tid] = b_ih1[tid] + b_hh1[tid]; }
    if (tid < 256) sw_hh[tid >> 3][tid & 7] = W_hh1[tid];
    __syncthreads();

    long n = (long)blockIdx.x * 256 + tid;
    const float4* xp = (const float4*)(x + n * 16);
    float4 xq[4];
    xq[0] = xp[0]; xq[1] = xp[1]; xq[2] = xp[2]; xq[3] = xp[3];
    float xv[16];
#pragma unroll
    for (int i = 0; i < 4; i++) {
        xv[4 * i + 0] = xq[i].x; xv[4 * i + 1] = xq[i].y;
        xv[4 * i + 2] = xq[i].z; xv[4 * i + 3] = xq[i].w;
    }

    float h[8], c[8];
#pragma unroll
    for (int d = 0; d < 8; d++) { h[d] = 0.f; c[d] = 0.f; }

#pragma unroll
    for (int t = 0; t < 16; t++) {
        float xt = xv[t];
        float hn[8];
#pragma unroll
        for (int d = 0; d < 8; d++) {
            float gi = fmaf(sw_ih[d],      xt, sbias[d]);
            float gf = fmaf(sw_ih[8 + d],  xt, sbias[8 + d]);
            float gg = fmaf(sw_ih[16 + d], xt, sbias[16 + d]);
            float go = fmaf(sw_ih[24 + d], xt, sbias[24 + d]);
#pragma unroll
            for (int e = 0; e < 8; e++) {
                float he = h[e];
                gi = fmaf(sw_hh[d][e],      he, gi);
                gf = fmaf(sw_hh[8 + d][e],  he, gf);
                gg = fmaf(sw_hh[16 + d][e], he, gg);
                go = fmaf(sw_hh[24 + d][e], he, go);
            }
            c[d]  = sigf(gf) * c[d] + sigf(gi) * tanh_(gg);
            hn[d] = sigf(go) * tanh_(c[d]);
        }
#pragma unroll
        for (int d = 0; d < 8; d++) h[d] = hn[d];
    }

    float4* o = (float4*)(g_h1 + n * 8);
    o[0] = make_float4(h[0], h[1], h[2], h[3]);
    o[1] = make_float4(h[4], h[5], h[6], h[7]);
}

// =================================================================
// Kernel 2: LSTM2, persistent, 128 CTAs x 1024 threads, 2 batches/CTA.
// Thread t: row-pair p = t & 255 (rows p, p+256), k-quarter kq = t >> 8.
//   Window: k in [36kq, 36kq+36), k>=136 padded with zero weights
//   (vec padded to 144 entries; vec[136..143]=0 forever).
// ALL weights live in REGISTERS as fp16 pairs: 18 half2 per row, 2 rows.
// vec is interleaved: vecI[k] = float2(batch0_val, batch1_val), k<8 = x_t,
//   k in [8,136) = h. One broadcast LDS.128 = 2 k's x 2 batches.
// Gate partials: g2[(kq*2+b)*256 + p] = float2(acc_row_p, acc_row_{p+256}).
//   Pair p<128 = (i_d, g_d); pair 128+d = (f_d, o_d).
// =================================================================
__global__ void __launch_bounds__(1024, 1) lstm2_kernel(
    const float* __restrict__ W_ih2, const float* __restrict__ W_hh2,
    const float* __restrict__ b_ih2, const float* __restrict__ b_hh2,
    const float* __restrict__ W1, const float* __restrict__ b1,
    const float* __restrict__ W2, const float* __restrict__ b2,
    float* __restrict__ out)
{
    __shared__ float2 vecI[144];          // interleaved (b0,b1), 1152 B
    __shared__ float2 g2[8 * 256];        // partials, 16 KB
    __shared__ float  red[8];

    const int t  = threadIdx.x;
    const int p  = t & 255;               // row pair: rows p, p+256
    const int kq = t >> 8;                // k-quarter
    const int b0 = blockIdx.x * 2;
    const int kb = 36 * kq;

    // ---- load this thread's weights into fp16 registers (once) ----
    unsigned int w0[18], w1[18];
#pragma unroll
    for (int m = 0; m < 18; m++) {
        int k = kb + 2 * m;
        float a0 = 0.f, a1 = 0.f, c0 = 0.f, c1 = 0.f;
        if (k < 136) {
            a0 = (k < 8) ? W_ih2[p * 8 + k] : W_hh2[p * 128 + k - 8];
            a1 = (k + 1 < 8) ? W_ih2[p * 8 + k + 1] : W_hh2[p * 128 + k - 7];
            c0 = (k < 8) ? W_ih2[(p + 256) * 8 + k] : W_hh2[(p + 256) * 128 + k - 8];
            c1 = (k + 1 < 8) ? W_ih2[(p + 256) * 8 + k + 1] : W_hh2[(p + 256) * 128 + k - 7];
        }
        __half2 h0 = __floats2half2_rn(a0, a1);
        __half2 h1 = __floats2half2_rn(c0, c1);
        w0[m] = *reinterpret_cast<unsigned int*>(&h0);
        w1[m] = *reinterpret_cast<unsigned int*>(&h1);
    }

    float bias0 = 0.f, bias1 = 0.f;
    if (kq == 0) {
        bias0 = b_ih2[p] + b_hh2[p];
        bias1 = b_ih2[p + 256] + b_hh2[p + 256];
    }

    // ---- init vec (zeros incl. pad) and stage x_0 ----
    if (t < 288) ((float*)vecI)[t] = 0.f;
    __syncthreads();
    if (t < 16) {
        int b = t >> 3, k = t & 7;
        ((float*)&vecI[k])[b] = g_h1[((long)(b0 + b) * 1024 + 0) * 8 + k];
    }
    float c = 0.f;     // cell state (threads t<256: d = t&127, b = t>>7)
    float xr = 0.f;    // x prefetch register (threads 256..271)
    if (t >= 256 && t < 272) {
        int u = t - 256, b = u >> 3, k = u & 7;
        xr = g_h1[((long)(b0 + b) * 1024 + 1) * 8 + k];
    }
    __syncthreads();

    const float4* V = (const float4*)vecI;       // V[i] = (b0_k, b1_k, b0_k+1, b1_k+1), k=2i
    const int vb = 18 * kq;                      // float4 base of this window
    float2* gout0 = g2 + (kq * 2 + 0) * 256 + p; // batch 0
    float2* gout1 = g2 + (kq * 2 + 1) * 256 + p; // batch 1

    for (int step = 0; step < 1024; step++) {
        // ---- phase A: partial gate sums, 2 rows x 2 batches ----
        float a00 = bias0, a01 = bias0;          // row p
        float a10 = bias1, a11 = bias1;          // row p+256
#pragma unroll
        for (int m = 0; m < 18; m++) {
            float4 v = V[vb + m];
            float2 wa = __half22float2(*reinterpret_cast<__half2*>(&w0[m]));
            float2 wb = __half22float2(*reinterpret_cast<__half2*>(&w1[m]));
            a00 = fmaf(wa.x, v.x, a00); a01 = fmaf(wa.x, v.y, a01);
            a00 = fmaf(wa.y, v.z, a00); a01 = fmaf(wa.y, v.w, a01);
            a10 = fmaf(wb.x, v.x, a10); a11 = fmaf(wb.x, v.y, a11);
            a10 = fmaf(wb.y, v.z, a10); a11 = fmaf(wb.y, v.w, a11);
        }
        *gout0 = make_float2(a00, a10);
        *gout1 = make_float2(a01, a11);
        __syncthreads();

        // ---- phase B: combine quarters, activations, h/x staging ----
        if (t < 256) {
            int d = t & 127, b = t >> 7;
            const float2* gb = g2 + b * 256;
            float2 ig0 = gb[0 * 512 + d],  fo0 = gb[0 * 512 + 128 + d];
            float2 ig1 = gb[1 * 512 + d],  fo1 = gb[1 * 512 + 128 + d];
            float2 ig2 = gb[2 * 512 + d],  fo2 = gb[2 * 512 + 128 + d];
            float2 ig3 = gb[3 * 512 + d],  fo3 = gb[3 * 512 + 128 + d];
            float gi = (ig0.x + ig1.x) + (ig2.x + ig3.x);
            float gg = (ig0.y + ig1.y) + (ig2.y + ig3.y);
            float gf = (fo0.x + fo1.x) + (fo2.x + fo3.x);
            float go = (fo0.y + fo1.y) + (fo2.y + fo3.y);
            c = sigf(gf) * c + sigf(gi) * tanh_(gg);
            float h = sigf(go) * tanh_(c);
            ((float*)&vecI[8 + d])[b] = h;
        } else if (t < 272) {
            int u = t - 256, b = u >> 3, k = u & 7;
            ((float*)&vecI[k])[b] = xr;                 // x_{step+1}
            int nt = step + 2;
            if (nt < 1024)
                xr = g_h1[((long)(b0 + b) * 1024 + nt) * 8 + k];
        }
        __syncthreads();
    }

    // ---- epilogue: out[b] = (h @ W1^T + b1) @ W2^T + b2 ----
    if (t < 128) {
        int b = t >> 6, jj = t & 63;
        const float* w1r = W1 + jj * 128;
        float m = b1[jj];
#pragma unroll
        for (int k = 0; k < 128; k++)
            m = fmaf(w1r[k], ((const float*)&vecI[8 + k])[b], m);
        float pr = m * W2[jj];
#pragma unroll
        for (int off = 16; off; off >>= 1)
            pr += __shfl_xor_sync(0xffffffff, pr, off);
        if ((t & 31) == 0) red[t >> 5] = pr;
    }
    __syncthreads();
    if (t < 2)
        out[b0 + t] = red[t * 2] + red[t * 2 + 1] + b2[0];
}

// =================================================================
extern "C" void kernel_launch(void* const* d_in, const int* in_sizes, int n_in,
                              void* d_out, int out_size) {
    const float* x     = (const float*)d_in[0];
    // d_in[1] = data (unused)
    const float* W_ih1 = (const float*)d_in[2];
    const float* W_hh1 = (const float*)d_in[3];
    const float* b_ih1 = (const float*)d_in[4];
    const float* b_hh1 = (const float*)d_in[5];
    const float* W_ih2 = (const float*)d_in[6];
    const float* W_hh2 = (const float*)d_in[7];
    const float* b_ih2 = (const float*)d_in[8];
    const float* b_hh2 = (const float*)d_in[9];
    const float* W1    = (const float*)d_in[10];
    const float* b1    = (const float*)d_in[11];
    const float* W2    = (const float*)d_in[12];
    const float* b2    = (const float*)d_in[13];
    float* out = (float*)d_out;

    lstm1_kernel<<<1024, 256>>>(x, W_ih1, W_hh1, b_ih1, b_hh1);

    lstm2_kernel<<<128, 1024>>>(W_ih2, W_hh2, b_ih2, b_hh2,
                                W1, b1, W2, b2, out);
}

// round 9
// speedup vs baseline: 3.1076x; 3.1076x over previous
#include <cuda_runtime.h>
#include <cuda_fp16.h>
#include <cstdint>

// ---------------- scratch (no cudaMalloc allowed) ----------------
__device__ __half g_h1h[256 * 1024 * 8];   // LSTM1 outputs as fp16, [B][S][8], 4MB

// ---------------- fast activations (validated R4: rel_err 3.7e-4) ------
__device__ __forceinline__ float fast_rcp(float x) {
    float r; asm("rcp.approx.ftz.f32 %0, %1;" : "=f"(r) : "f"(x)); return r;
}
__device__ __forceinline__ float fast_ex2(float x) {
    float r; asm("ex2.approx.ftz.f32 %0, %1;" : "=f"(r) : "f"(x)); return r;
}
__device__ __forceinline__ float sigf(float x) {
    return fast_rcp(1.0f + fast_ex2(-1.4426950408889634f * x));
}
__device__ __forceinline__ float tanh_(float x) {
    return fmaf(2.0f, sigf(2.0f * x), -1.0f);
}
__device__ __forceinline__ __half2 u2h(unsigned u) {
    return *reinterpret_cast<__half2*>(&u);
}

// =================================================================
// Kernel 1: LSTM1. One thread per (b,s) sequence: 16 steps, input=1, H=8.
// Weights broadcast from smem as float4 (gate-major vectors); fp16 output.
// =================================================================
__device__ __forceinline__ void lstm_upd(float& c, float& h,
                                         float gi, float gf, float gg, float go) {
    c = sigf(gf) * c + sigf(gi) * tanh_(gg);
    h = sigf(go) * tanh_(c);
}

__global__ __launch_bounds__(256) void lstm1_kernel(
    const float* __restrict__ x,
    const float* __restrict__ W_ih1, const float* __restrict__ W_hh1,
    const float* __restrict__ b_ih1, const float* __restrict__ b_hh1)
{
    __shared__ float sI[32];          // W_ih per gate
    __shared__ float sB[32];          // fused bias per gate
    __shared__ float sT[8][32];       // sT[e][gate] = W_hh1[gate][e]
    int tid = threadIdx.x;
    if (tid < 32) { sI[tid] = W_ih1[tid]; sB[tid] = b_ih1[tid] + b_hh1[tid]; }
    sT[tid & 7][tid >> 3] = W_hh1[tid];
    __syncthreads();

    long n = (long)blockIdx.x * 256 + tid;
    const float4* xp = (const float4*)(x + n * 16);
    float4 xq[4];
    xq[0] = xp[0]; xq[1] = xp[1]; xq[2] = xp[2]; xq[3] = xp[3];
    float xv[16];
#pragma unroll
    for (int i = 0; i < 4; i++) {
        xv[4 * i + 0] = xq[i].x; xv[4 * i + 1] = xq[i].y;
        xv[4 * i + 2] = xq[i].z; xv[4 * i + 3] = xq[i].w;
    }

    float h[8], c[8];
#pragma unroll
    for (int d = 0; d < 8; d++) { h[d] = 0.f; c[d] = 0.f; }

    const float4* I4 = (const float4*)sI;
    const float4* B4 = (const float4*)sB;

#pragma unroll
    for (int t = 0; t < 16; t++) {
        float xt = xv[t];
        float4 acc[8];
#pragma unroll
        for (int q = 0; q < 8; q++) {
            float4 w = I4[q], bb = B4[q];
            acc[q].x = fmaf(w.x, xt, bb.x);
            acc[q].y = fmaf(w.y, xt, bb.y);
            acc[q].z = fmaf(w.z, xt, bb.z);
            acc[q].w = fmaf(w.w, xt, bb.w);
        }
#pragma unroll
        for (int e = 0; e < 8; e++) {
            float he = h[e];
            const float4* T4 = (const float4*)sT[e];
#pragma unroll
            for (int q = 0; q < 8; q++) {
                float4 w = T4[q];
                acc[q].x = fmaf(w.x, he, acc[q].x);
                acc[q].y = fmaf(w.y, he, acc[q].y);
                acc[q].z = fmaf(w.z, he, acc[q].z);
                acc[q].w = fmaf(w.w, he, acc[q].w);
            }
        }
#pragma unroll
        for (int q = 0; q < 2; q++) {   // i=acc[0..1], f=[2..3], g=[4..5], o=[6..7]
            float4 ai = acc[q], af = acc[2 + q], ag = acc[4 + q], ao = acc[6 + q];
            lstm_upd(c[4 * q + 0], h[4 * q + 0], ai.x, af.x, ag.x, ao.x);
            lstm_upd(c[4 * q + 1], h[4 * q + 1], ai.y, af.y, ag.y, ao.y);
            lstm_upd(c[4 * q + 2], h[4 * q + 2], ai.z, af.z, ag.z, ao.z);
            lstm_upd(c[4 * q + 3], h[4 * q + 3], ai.w, af.w, ag.w, ao.w);
        }
    }

    __half2 p0 = __floats2half2_rn(h[0], h[1]);
    __half2 p1 = __floats2half2_rn(h[2], h[3]);
    __half2 p2 = __floats2half2_rn(h[4], h[5]);
    __half2 p3 = __floats2half2_rn(h[6], h[7]);
    uint4 u;
    u.x = *reinterpret_cast<uint32_t*>(&p0);
    u.y = *reinterpret_cast<uint32_t*>(&p1);
    u.z = *reinterpret_cast<uint32_t*>(&p2);
    u.w = *reinterpret_cast<uint32_t*>(&p3);
    *reinterpret_cast<uint4*>(g_h1h + n * 8) = u;
}

// =================================================================
// Kernel 2: LSTM2, persistent, 128 CTAs x 512 threads, 2 batches/CTA.
// Thread j (0..511) owns gate-row j, ALL 136 k's, both batches.
// Weights: 68 half2 REGISTERS per thread (fp16, packed (k, k+1)).
// vec: fp16 in smem, vecH[b][k/2] = half2(v_k, v_{k+1}); k<8 = x_t, else h.
// Dot products: __hfma2, lanes = (even-k partial, odd-k partial);
//   4 independent chains (2 per batch), flushed to fp32 every 32 k.
// Gate exchange: gst[j] = float2(a_batch0, a_batch1).
// Phase B: thread (d = t&127, b = t>>7) combines gates i,f,g,o (rows d,
//   128+d, 256+d, 384+d), updates c/h, writes fp16 h back to vecH.
// =================================================================
__global__ void __launch_bounds__(512, 1) lstm2_kernel(
    const float* __restrict__ W_ih2, const float* __restrict__ W_hh2,
    const float* __restrict__ b_ih2, const float* __restrict__ b_hh2,
    const float* __restrict__ W1, const float* __restrict__ b1,
    const float* __restrict__ W2, const float* __restrict__ b2,
    float* __restrict__ out)
{
    __shared__ __half2 vecH[2][80];   // per batch: 68 used, pad to 80
    __shared__ float2  gst[512];
    __shared__ float   hb[256];
    __shared__ float   red[8];

    const int t  = threadIdx.x;
    const int j  = t;                 // gate row
    const int b0 = blockIdx.x * 2;

    // ---- pack this row's weights into 68 half2 registers ----
    __half2 wreg[68];
    {
        const float4* wi4 = (const float4*)(W_ih2 + j * 8);
#pragma unroll
        for (int q = 0; q < 2; q++) {
            float4 v = wi4[q];
            wreg[2 * q + 0] = __floats2half2_rn(v.x, v.y);
            wreg[2 * q + 1] = __floats2half2_rn(v.z, v.w);
        }
        const float4* wh4 = (const float4*)(W_hh2 + j * 128);
#pragma unroll
        for (int q = 0; q < 32; q++) {
            float4 v = wh4[q];
            wreg[4 + 2 * q + 0] = __floats2half2_rn(v.x, v.y);
            wreg[4 + 2 * q + 1] = __floats2half2_rn(v.z, v.w);
        }
    }
    const float bias = b_ih2[j] + b_hh2[j];

    // ---- init vec (h = 0), stage x_0, prefetch x_1 ----
    if (t < 160) ((float*)vecH)[t] = 0.f;
    __syncthreads();
    if (t < 16) {
        int b = t >> 3, k = t & 7;
        ((__half*)vecH[b])[k] = g_h1h[((long)(b0 + b) * 1024 + 0) * 8 + k];
    }
    float c_ = 0.f, h_ = 0.f;              // state for threads t<256 (d=t&127,b=t>>7)
    __half xr = __float2half_rn(0.f);      // x prefetch (threads 256..271)
    if (t >= 256 && t < 272) {
        int u = t - 256, b = u >> 3, k = u & 7;
        xr = g_h1h[((long)(b0 + b) * 1024 + 1) * 8 + k];
    }
    __syncthreads();

    const uint4* V0 = (const uint4*)(vecH[0]);   // uint4 = 4 half2 = 8 k
    const uint4* V1 = (const uint4*)(vecH[1]);
    const __half2 hz = __float2half2_rn(0.f);

    for (int step = 0; step < 1024; step++) {
        // ---- phase A: full-row dot products, 2 batches ----
        float a0 = bias, a1 = bias;
#pragma unroll
        for (int blk = 0; blk < 4; blk++) {       // q = 4*blk .. 4*blk+3 (32 k)
            __half2 sA0 = hz, sB0 = hz, sA1 = hz, sB1 = hz;
#pragma unroll
            for (int qq = 0; qq < 4; qq++) {
                int q = blk * 4 + qq;
                uint4 u0 = V0[q];
                uint4 u1 = V1[q];
                __half2 w0 = wreg[4 * q + 0], w1 = wreg[4 * q + 1];
                __half2 w2 = wreg[4 * q + 2], w3 = wreg[4 * q + 3];
                sA0 = __hfma2(w0, u2h(u0.x), sA0);
                sB0 = __hfma2(w1, u2h(u0.y), sB0);
                sA0 = __hfma2(w2, u2h(u0.z), sA0);
                sB0 = __hfma2(w3, u2h(u0.w), sB0);
                sA1 = __hfma2(w0, u2h(u1.x), sA1);
                sB1 = __hfma2(w1, u2h(u1.y), sB1);
                sA1 = __hfma2(w2, u2h(u1.z), sA1);
                sB1 = __hfma2(w3, u2h(u1.w), sB1);
            }
            float2 f0 = __half22float2(__hadd2(sA0, sB0));
            float2 f1 = __half22float2(__hadd2(sA1, sB1));
            a0 += f0.x; a0 += f0.y;
            a1 += f1.x; a1 += f1.y;
        }
        {   // tail: q = 16 (k 128..135)
            uint4 u0 = V0[16];
            uint4 u1 = V1[16];
            __half2 w0 = wreg[64], w1 = wreg[65], w2 = wreg[66], w3 = wreg[67];
            __half2 sA0 = __hfma2(w0, u2h(u0.x), hz);
            __half2 sB0 = __hfma2(w1, u2h(u0.y), hz);
            sA0 = __hfma2(w2, u2h(u0.z), sA0);
            sB0 = __hfma2(w3, u2h(u0.w), sB0);
            __half2 sA1 = __hfma2(w0, u2h(u1.x), hz);
            __half2 sB1 = __hfma2(w1, u2h(u1.y), hz);
            sA1 = __hfma2(w2, u2h(u1.z), sA1);
            sB1 = __hfma2(w3, u2h(u1.w), sB1);
            float2 f0 = __half22float2(__hadd2(sA0, sB0));
            float2 f1 = __half22float2(__hadd2(sA1, sB1));
            a0 += f0.x; a0 += f0.y;
            a1 += f1.x; a1 += f1.y;
        }
        gst[j] = make_float2(a0, a1);
        __syncthreads();

        // ---- phase B: activations + h/x staging ----
        if (t < 256) {
            int d = t & 127, b = t >> 7;
            float2 g_i = gst[d];
            float2 g_f = gst[128 + d];
            float2 g_g = gst[256 + d];
            float2 g_o = gst[384 + d];
            float gi = b ? g_i.y : g_i.x;
            float gf = b ? g_f.y : g_f.x;
            float gg = b ? g_g.y : g_g.x;
            float go = b ? g_o.y : g_o.x;
            c_ = sigf(gf) * c_ + sigf(gi) * tanh_(gg);
            h_ = sigf(go) * tanh_(c_);
            ((__half*)vecH[b])[8 + d] = __float2half_rn(h_);
        } else if (t < 272) {
            int u = t - 256, b = u >> 3, k = u & 7;
            ((__half*)vecH[b])[k] = xr;               // x_{step+1}
            if (step + 2 < 1024)
                xr = g_h1h[((long)(b0 + b) * 1024 + step + 2) * 8 + k];
        }
        __syncthreads();
    }

    // ---- epilogue: out[b] = (h @ W1^T + b1) @ W2^T + b2 ----
    if (t < 256) hb[(t >> 7) * 128 + (t & 127)] = h_;
    __syncthreads();
    if (t < 128) {
        int b = t >> 6, jj = t & 63;
        const float* hv  = hb + b * 128;
        const float* w1r = W1 + jj * 128;
        float m_ = b1[jj];
#pragma unroll
        for (int k = 0; k < 128; k++) m_ = fmaf(w1r[k], hv[k], m_);
        float pr = m_ * W2[jj];
#pragma unroll
        for (int off = 16; off; off >>= 1)
            pr += __shfl_xor_sync(0xffffffff, pr, off);
        if ((t & 31) == 0) red[t >> 5] = pr;
    }
    __syncthreads();
    if (t < 2)
        out[b0 + t] = red[t * 2] + red[t * 2 + 1] + b2[0];
}

// =================================================================
extern "C" void kernel_launch(void* const* d_in, const int* in_sizes, int n_in,
                              void* d_out, int out_size) {
    const float* x     = (const float*)d_in[0];
    // d_in[1] = data (unused)
    const float* W_ih1 = (const float*)d_in[2];
    const float* W_hh1 = (const float*)d_in[3];
    const float* b_ih1 = (const float*)d_in[4];
    const float* b_hh1 = (const float*)d_in[5];
    const float* W_ih2 = (const float*)d_in[6];
    const float* W_hh2 = (const float*)d_in[7];
    const float* b_ih2 = (const float*)d_in[8];
    const float* b_hh2 = (const float*)d_in[9];
    const float* W1    = (const float*)d_in[10];
    const float* b1    = (const float*)d_in[11];
    const float* W2    = (const float*)d_in[12];
    const float* b2    = (const float*)d_in[13];
    float* out = (float*)d_out;

    lstm1_kernel<<<1024, 256>>>(x, W_ih1, W_hh1, b_ih1, b_hh1);

    lstm2_kernel<<<128, 512>>>(W_ih2, W_hh2, b_ih2, b_hh2,
                               W1, b1, W2, b2, out);
}

// round 10
// speedup vs baseline: 3.2833x; 1.0566x over previous
#include <cuda_runtime.h>
#include <cuda_fp16.h>
#include <cstdint>

// ---------------- scratch (no cudaMalloc allowed) ----------------
__device__ __half g_h1h[256 * 1024 * 8];   // LSTM1 outputs as fp16, [B][S][8], 4MB

// ---------------- fast activations: MUFU.TANH based (validated R5) -----
__device__ __forceinline__ float tanhapx(float x) {
    float r; asm("tanh.approx.f32 %0, %1;" : "=f"(r) : "f"(x)); return r;
}
// sigmoid(x) = 0.5*tanh(0.5x) + 0.5   (1 MUFU + 1 FFMA)
__device__ __forceinline__ float sigf(float x) {
    return fmaf(0.5f, tanhapx(0.5f * x), 0.5f);
}
__device__ __forceinline__ float tanh_(float x) { return tanhapx(x); }

__device__ __forceinline__ __half2 u2h(unsigned u) {
    return *reinterpret_cast<__half2*>(&u);
}

// =================================================================
// Kernel 1: LSTM1. One thread per (b,s) sequence: 16 steps, input=1, H=8.
// Weights broadcast from smem as float4 (gate-major vectors); fp16 output.
// =================================================================
__device__ __forceinline__ void lstm_upd(float& c, float& h,
                                         float gi, float gf, float gg, float go) {
    float ti = tanhapx(0.5f * gi);
    float tf = tanhapx(0.5f * gf);
    float tg = tanhapx(gg);
    float to = tanhapx(0.5f * go);
    float p  = fmaf(0.5f * ti, tg, 0.5f * tg);          // sig(i)*tanh(g)
    c = fmaf(0.5f * tf, c, fmaf(0.5f, c, p));           // sig(f)*c + p
    float tc = tanhapx(c);
    h = fmaf(0.5f * to, tc, 0.5f * tc);                 // sig(o)*tanh(c)
}

__global__ __launch_bounds__(256) void lstm1_kernel(
    const float* __restrict__ x,
    const float* __restrict__ W_ih1, const float* __restrict__ W_hh1,
    const float* __restrict__ b_ih1, const float* __restrict__ b_hh1)
{
    __shared__ float sI[32];          // W_ih per gate
    __shared__ float sB[32];          // fused bias per gate
    __shared__ float sT[8][32];       // sT[e][gate] = W_hh1[gate][e]
    int tid = threadIdx.x;
    if (tid < 32) { sI[tid] = W_ih1[tid]; sB[tid] = b_ih1[tid] + b_hh1[tid]; }
    sT[tid & 7][tid >> 3] = W_hh1[tid];
    __syncthreads();

    long n = (long)blockIdx.x * 256 + tid;
    const float4* xp = (const float4*)(x + n * 16);
    float4 xq[4];
    xq[0] = xp[0]; xq[1] = xp[1]; xq[2] = xp[2]; xq[3] = xp[3];
    float xv[16];
#pragma unroll
    for (int i = 0; i < 4; i++) {
        xv[4 * i + 0] = xq[i].x; xv[4 * i + 1] = xq[i].y;
        xv[4 * i + 2] = xq[i].z; xv[4 * i + 3] = xq[i].w;
    }

    float h[8], c[8];
#pragma unroll
    for (int d = 0; d < 8; d++) { h[d] = 0.f; c[d] = 0.f; }

    const float4* I4 = (const float4*)sI;
    const float4* B4 = (const float4*)sB;

#pragma unroll
    for (int t = 0; t < 16; t++) {
        float xt = xv[t];
        float4 acc[8];
#pragma unroll
        for (int q = 0; q < 8; q++) {
            float4 w = I4[q], bb = B4[q];
            acc[q].x = fmaf(w.x, xt, bb.x);
            acc[q].y = fmaf(w.y, xt, bb.y);
            acc[q].z = fmaf(w.z, xt, bb.z);
            acc[q].w = fmaf(w.w, xt, bb.w);
        }
#pragma unroll
        for (int e = 0; e < 8; e++) {
            float he = h[e];
            const float4* T4 = (const float4*)sT[e];
#pragma unroll
            for (int q = 0; q < 8; q++) {
                float4 w = T4[q];
                acc[q].x = fmaf(w.x, he, acc[q].x);
                acc[q].y = fmaf(w.y, he, acc[q].y);
                acc[q].z = fmaf(w.z, he, acc[q].z);
                acc[q].w = fmaf(w.w, he, acc[q].w);
            }
        }
#pragma unroll
        for (int q = 0; q < 2; q++) {   // i=acc[0..1], f=[2..3], g=[4..5], o=[6..7]
            float4 ai = acc[q], af = acc[2 + q], ag = acc[4 + q], ao = acc[6 + q];
            lstm_upd(c[4 * q + 0], h[4 * q + 0], ai.x, af.x, ag.x, ao.x);
            lstm_upd(c[4 * q + 1], h[4 * q + 1], ai.y, af.y, ag.y, ao.y);
            lstm_upd(c[4 * q + 2], h[4 * q + 2], ai.z, af.z, ag.z, ao.z);
            lstm_upd(c[4 * q + 3], h[4 * q + 3], ai.w, af.w, ag.w, ao.w);
        }
    }

    __half2 p0 = __floats2half2_rn(h[0], h[1]);
    __half2 p1 = __floats2half2_rn(h[2], h[3]);
    __half2 p2 = __floats2half2_rn(h[4], h[5]);
    __half2 p3 = __floats2half2_rn(h[6], h[7]);
    uint4 u;
    u.x = *reinterpret_cast<uint32_t*>(&p0);
    u.y = *reinterpret_cast<uint32_t*>(&p1);
    u.z = *reinterpret_cast<uint32_t*>(&p2);
    u.w = *reinterpret_cast<uint32_t*>(&p3);
    *reinterpret_cast<uint4*>(g_h1h + n * 8) = u;
}

// =================================================================
// Kernel 2: LSTM2, persistent, 128 CTAs x 512 threads, 2 batches/CTA.
// Thread j (0..511) owns gate-row j, ALL 136 k's, both batches.
// Weights: 68 half2 REGISTERS per thread (fp16, packed (k, k+1)).
// vec: fp16 in smem, vecH[b][k/2] = half2(v_k, v_{k+1}); k<8 = x_t, else h.
// Dot products: __hfma2, 4 chains (2/batch), flushed to fp32 every 32 k.
// Gate exchange: gst[j] = float2(a_batch0, a_batch1).
// Phase B: thread (d = t&127, b = t>>7) combines gates i,f,g,o, updates c/h.
// =================================================================
__global__ void __launch_bounds__(512, 1) lstm2_kernel(
    const float* __restrict__ W_ih2, const float* __restrict__ W_hh2,
    const float* __restrict__ b_ih2, const float* __restrict__ b_hh2,
    const float* __restrict__ W1, const float* __restrict__ b1,
    const float* __restrict__ W2, const float* __restrict__ b2,
    float* __restrict__ out)
{
    __shared__ __half2 vecH[2][80];   // per batch: 68 used, pad to 80
    __shared__ float2  gst[512];
    __shared__ float   hb[256];
    __shared__ float   red[8];

    const int t  = threadIdx.x;
    const int j  = t;                 // gate row
    const int b0 = blockIdx.x * 2;

    // ---- pack this row's weights into 68 half2 registers ----
    __half2 wreg[68];
    {
        const float4* wi4 = (const float4*)(W_ih2 + j * 8);
#pragma unroll
        for (int q = 0; q < 2; q++) {
            float4 v = wi4[q];
            wreg[2 * q + 0] = __floats2half2_rn(v.x, v.y);
            wreg[2 * q + 1] = __floats2half2_rn(v.z, v.w);
        }
        const float4* wh4 = (const float4*)(W_hh2 + j * 128);
#pragma unroll
        for (int q = 0; q < 32; q++) {
            float4 v = wh4[q];
            wreg[4 + 2 * q + 0] = __floats2half2_rn(v.x, v.y);
            wreg[4 + 2 * q + 1] = __floats2half2_rn(v.z, v.w);
        }
    }
    const float bias = b_ih2[j] + b_hh2[j];

    // ---- init vec (h = 0), stage x_0, prefetch x_1 ----
    if (t < 160) ((float*)vecH)[t] = 0.f;
    __syncthreads();
    if (t < 16) {
        int b = t >> 3, k = t & 7;
        ((__half*)vecH[b])[k] = g_h1h[((long)(b0 + b) * 1024 + 0) * 8 + k];
    }
    float c_ = 0.f, h_ = 0.f;              // state for threads t<256 (d=t&127,b=t>>7)
    __half xr = __float2half_rn(0.f);      // x prefetch (threads 256..271)
    if (t >= 256 && t < 272) {
        int u = t - 256, b = u >> 3, k = u & 7;
        xr = g_h1h[((long)(b0 + b) * 1024 + 1) * 8 + k];
    }
    __syncthreads();

    const uint4* V0 = (const uint4*)(vecH[0]);   // uint4 = 4 half2 = 8 k
    const uint4* V1 = (const uint4*)(vecH[1]);
    const __half2 hz = __float2half2_rn(0.f);

    for (int step = 0; step < 1024; step++) {
        // ---- phase A: full-row dot products, 2 batches ----
        float a0 = bias, a1 = bias;
#pragma unroll
        for (int blk = 0; blk < 4; blk++) {       // q = 4*blk .. 4*blk+3 (32 k)
            __half2 sA0 = hz, sB0 = hz, sA1 = hz, sB1 = hz;
#pragma unroll
            for (int qq = 0; qq < 4; qq++) {
                int q = blk * 4 + qq;
                uint4 u0 = V0[q];
                uint4 u1 = V1[q];
                __half2 w0 = wreg[4 * q + 0], w1 = wreg[4 * q + 1];
                __half2 w2 = wreg[4 * q + 2], w3 = wreg[4 * q + 3];
                sA0 = __hfma2(w0, u2h(u0.x), sA0);
                sB0 = __hfma2(w1, u2h(u0.y), sB0);
                sA0 = __hfma2(w2, u2h(u0.z), sA0);
                sB0 = __hfma2(w3, u2h(u0.w), sB0);
                sA1 = __hfma2(w0, u2h(u1.x), sA1);
                sB1 = __hfma2(w1, u2h(u1.y), sB1);
                sA1 = __hfma2(w2, u2h(u1.z), sA1);
                sB1 = __hfma2(w3, u2h(u1.w), sB1);
            }
            float2 f0 = __half22float2(__hadd2(sA0, sB0));
            float2 f1 = __half22float2(__hadd2(sA1, sB1));
            a0 += f0.x; a0 += f0.y;
            a1 += f1.x; a1 += f1.y;
        }
        {   // tail: q = 16 (k 128..135)
            uint4 u0 = V0[16];
            uint4 u1 = V1[16];
            __half2 w0 = wreg[64], w1 = wreg[65], w2 = wreg[66], w3 = wreg[67];
            __half2 sA0 = __hfma2(w0, u2h(u0.x), hz);
            __half2 sB0 = __hfma2(w1, u2h(u0.y), hz);
            sA0 = __hfma2(w2, u2h(u0.z), sA0);
            sB0 = __hfma2(w3, u2h(u0.w), sB0);
            __half2 sA1 = __hfma2(w0, u2h(u1.x), hz);
            __half2 sB1 = __hfma2(w1, u2h(u1.y), hz);
            sA1 = __hfma2(w2, u2h(u1.z), sA1);
            sB1 = __hfma2(w3, u2h(u1.w), sB1);
            float2 f0 = __half22float2(__hadd2(sA0, sB0));
            float2 f1 = __half22float2(__hadd2(sA1, sB1));
            a0 += f0.x; a0 += f0.y;
            a1 += f1.x; a1 += f1.y;
        }
        gst[j] = make_float2(a0, a1);
        __syncthreads();

        // ---- phase B: activations + h/x staging ----
        if (t < 256) {
            int d = t & 127, b = t >> 7;
            float2 g_i = gst[d];
            float2 g_f = gst[128 + d];
            float2 g_g = gst[256 + d];
            float2 g_o = gst[384 + d];
            float gi = b ? g_i.y : g_i.x;
            float gf = b ? g_f.y : g_f.x;
            float gg = b ? g_g.y : g_g.x;
            float go = b ? g_o.y : g_o.x;
            float ti = tanhapx(0.5f * gi);
            float tf = tanhapx(0.5f * gf);
            float tg = tanhapx(gg);
            float to = tanhapx(0.5f * go);
            float p  = fmaf(0.5f * ti, tg, 0.5f * tg);
            c_ = fmaf(0.5f * tf, c_, fmaf(0.5f, c_, p));
            float tc = tanhapx(c_);
            h_ = fmaf(0.5f * to, tc, 0.5f * tc);
            ((__half*)vecH[b])[8 + d] = __float2half_rn(h_);
        } else if (t < 272) {
            int u = t - 256, b = u >> 3, k = u & 7;
            ((__half*)vecH[b])[k] = xr;               // x_{step+1}
            if (step + 2 < 1024)
                xr = g_h1h[((long)(b0 + b) * 1024 + step + 2) * 8 + k];
        }
        __syncthreads();
    }

    // ---- epilogue: out[b] = (h @ W1^T + b1) @ W2^T + b2 ----
    if (t < 256) hb[(t >> 7) * 128 + (t & 127)] = h_;
    __syncthreads();
    if (t < 128) {
        int b = t >> 6, jj = t & 63;
        const float* hv  = hb + b * 128;
        const float* w1r = W1 + jj * 128;
        float m_ = b1[jj];
#pragma unroll
        for (int k = 0; k < 128; k++) m_ = fmaf(w1r[k], hv[k], m_);
        float pr = m_ * W2[jj];
#pragma unroll
        for (int off = 16; off; off >>= 1)
            pr += __shfl_xor_sync(0xffffffff, pr, off);
        if ((t & 31) == 0) red[t >> 5] = pr;
    }
    __syncthreads();
    if (t < 2)
        out[b0 + t] = red[t * 2] + red[t * 2 + 1] + b2[0];
}

// =================================================================
extern "C" void kernel_launch(void* const* d_in, const int* in_sizes, int n_in,
                              void* d_out, int out_size) {
    const float* x     = (const float*)d_in[0];
    // d_in[1] = data (unused)
    const float* W_ih1 = (const float*)d_in[2];
    const float* W_hh1 = (const float*)d_in[3];
    const float* b_ih1 = (const float*)d_in[4];
    const float* b_hh1 = (const float*)d_in[5];
    const float* W_ih2 = (const float*)d_in[6];
    const float* W_hh2 = (const float*)d_in[7];
    const float* b_ih2 = (const float*)d_in[8];
    const float* b_hh2 = (const float*)d_in[9];
    const float* W1    = (const float*)d_in[10];
    const float* b1    = (const float*)d_in[11];
    const float* W2    = (const float*)d_in[12];
    const float* b2    = (const float*)d_in[13];
    float* out = (float*)d_out;

    lstm1_kernel<<<1024, 256>>>(x, W_ih1, W_hh1, b_ih1, b_hh1);

    lstm2_kernel<<<128, 512>>>(W_ih2, W_hh2, b_ih2, b_hh2,
                               W1, b1, W2, b2, out);
}